// round 2
// baseline (speedup 1.0000x reference)
#include <cuda_runtime.h>
#include <cuda_bf16.h>
#include <cstdint>
#include <math.h>

// Problem dims
#define BB 1024
#define DD 512
#define HH 1024
#define TT 64

// Tiles
#define BM 64
#define BN 64
#define BK 64            // bf16 K-chunk (128 bytes/row)
#define NTHREADS 128     // 4 warps, 2x2 warp grid, warp tile 32x32

// ---------------- persistent state (no runtime allocation) ----------------
__device__ float g_y[BB*DD];
__device__ float g_ks[BB*DD];
__device__ __nv_bfloat16 g_x[BB*DD];     // current stage evaluation point (bf16)
__device__ __nv_bfloat16 g_h[BB*HH];     // tanh hidden (bf16)
__device__ __nv_bfloat16 g_W1T[HH*DD];   // W1^T [H][D]  (K-major rows)
__device__ __nv_bfloat16 g_W2T[DD*HH];   // W2^T [D][H]

#define SWZ(x) ((x) ^ (((x) >> 3) & 0x70))

__device__ __forceinline__ uint32_t smem_u32(const void* p) {
    uint32_t a;
    asm("{ .reg .u64 t; cvta.to.shared.u64 t, %1; cvt.u32.u64 %0, t; }" : "=r"(a) : "l"(p));
    return a;
}
__device__ __forceinline__ void cp16(uint32_t s, const void* g) {
    asm volatile("cp.async.cg.shared.global [%0], [%1], 16;" :: "r"(s), "l"(g));
}
#define CP_COMMIT()  asm volatile("cp.async.commit_group;" ::: "memory")
#define CP_WAIT(n)   asm volatile("cp.async.wait_group %0;" :: "n"(n) : "memory")

__device__ __forceinline__ void ldm_x4(uint32_t& r0, uint32_t& r1, uint32_t& r2, uint32_t& r3,
                                       uint32_t addr) {
    asm volatile("ldmatrix.sync.aligned.m8n8.x4.shared.b16 {%0,%1,%2,%3}, [%4];"
                 : "=r"(r0), "=r"(r1), "=r"(r2), "=r"(r3) : "r"(addr));
}
__device__ __forceinline__ void mma16816(float* c, uint32_t a0, uint32_t a1, uint32_t a2,
                                         uint32_t a3, uint32_t b0, uint32_t b1) {
    asm volatile("mma.sync.aligned.m16n8k16.row.col.f32.bf16.bf16.f32 "
                 "{%0,%1,%2,%3}, {%4,%5,%6,%7}, {%8,%9}, {%0,%1,%2,%3};"
                 : "+f"(c[0]), "+f"(c[1]), "+f"(c[2]), "+f"(c[3])
                 : "r"(a0), "r"(a1), "r"(a2), "r"(a3), "r"(b0), "r"(b1));
}

// ---------------- init kernels ----------------
__global__ void init_weights(const float* __restrict__ W1, const float* __restrict__ W2) {
    int i = blockIdx.x * blockDim.x + threadIdx.x;
    if (i >= DD * HH) return;
    { int d = i / HH, h = i % HH; g_W1T[h * DD + d] = __float2bfloat16(W1[i]); }
    { int h = i / DD, d = i % DD; g_W2T[d * HH + h] = __float2bfloat16(W2[i]); }
}
__global__ void init_state(const float* __restrict__ fp, float* __restrict__ out) {
    int i = blockIdx.x * blockDim.x + threadIdx.x;
    if (i >= BB * DD) return;
    float v = fp[i];
    g_y[i] = v;
    g_x[i] = __float2bfloat16(v);
    out[i] = v;                         // pred_y[t=0]
}

// ---------------- fused GEMM kernel ----------------
// mode 0: h = tanh(x @ W1 + b1)        A=g_x [B,D], Bop=g_W1T [H,D]  -> g_h
// mode 1: k = h @ W2 + b2 + RK4 update A=g_h [B,H], Bop=g_W2T [D,H]  -> g_ks/g_y/g_x/out
__global__ __launch_bounds__(NTHREADS)
void ode_gemm(int mode, int stage, int step,
              const float* __restrict__ bias,
              const float* __restrict__ ts,
              float* __restrict__ out)
{
    __shared__ __align__(1024) char smem[2 * 16384];   // per buf: A 8KB, B 8KB

    const int tid  = threadIdx.x;
    const int wid  = tid >> 5, lane = tid & 31;
    const int wM   = wid & 1, wN = wid >> 1;           // 2x2 warp grid

    const int K = (mode == 0) ? DD : HH;
    const __nv_bfloat16* __restrict__ A  = (mode == 0) ? g_x   : g_h;
    const __nv_bfloat16* __restrict__ Bw = (mode == 0) ? g_W1T : g_W2T;
    const int m0 = blockIdx.y * BM;
    const int n0 = blockIdx.x * BN;
    const int nch = K / BK;

    const uint32_t sbase = smem_u32(smem);

    float acc[2][4][4];
    #pragma unroll
    for (int i = 0; i < 2; ++i)
        #pragma unroll
        for (int j = 0; j < 4; ++j)
            #pragma unroll
            for (int q = 0; q < 4; ++q) acc[i][j][q] = 0.f;

    // tile loader: chunk c into buffer buf
    auto load_tiles = [&](int c, int buf) {
        const uint32_t sA = sbase + buf * 16384;
        const uint32_t sB = sA + 8192;
        const __nv_bfloat16* Ag = A  + (size_t)m0 * K + c * BK;
        const __nv_bfloat16* Bg = Bw + (size_t)n0 * K + c * BK;
        #pragma unroll
        for (int p = 0; p < 4; ++p) {                 // A: 64 rows x 128B
            int idx = p * NTHREADS + tid;
            int r = idx >> 3, kb = (idx & 7) << 4;    // kb = byte col
            cp16(sA + SWZ(r * 128 + kb), Ag + (size_t)r * K + (kb >> 1));
        }
        #pragma unroll
        for (int p = 0; p < 4; ++p) {                 // B: 64 rows x 128B
            int idx = p * NTHREADS + tid;
            int r = idx >> 3, kb = (idx & 7) << 4;
            cp16(sB + SWZ(r * 128 + kb), Bg + (size_t)r * K + (kb >> 1));
        }
    };

    load_tiles(0, 0);
    CP_COMMIT();

    for (int c = 0; c < nch; ++c) {
        if (c + 1 < nch) {
            load_tiles(c + 1, (c + 1) & 1);
            CP_COMMIT();
            CP_WAIT(1);
        } else {
            CP_WAIT(0);
        }
        __syncthreads();

        const uint32_t sA = sbase + (c & 1) * 16384;
        const uint32_t sB = sA + 8192;

        #pragma unroll
        for (int ks = 0; ks < 4; ++ks) {              // 4 k-steps of 16
            const int kb = (ks * 16 + ((lane >> 4) << 3)) * 2;
            uint32_t af[2][4], bf[2][4];
            #pragma unroll
            for (int mi = 0; mi < 2; ++mi) {
                int r = wM * 32 + mi * 16 + (lane & 15);
                ldm_x4(af[mi][0], af[mi][1], af[mi][2], af[mi][3],
                       sA + SWZ(r * 128 + kb));
            }
            #pragma unroll
            for (int nj = 0; nj < 2; ++nj) {
                int r = wN * 32 + nj * 16 + (lane & 15);
                ldm_x4(bf[nj][0], bf[nj][1], bf[nj][2], bf[nj][3],
                       sB + SWZ(r * 128 + kb));
            }
            #pragma unroll
            for (int mi = 0; mi < 2; ++mi)
                #pragma unroll
                for (int nj = 0; nj < 2; ++nj) {
                    mma16816(acc[mi][2 * nj],     af[mi][0], af[mi][1], af[mi][2], af[mi][3],
                             bf[nj][0], bf[nj][2]);
                    mma16816(acc[mi][2 * nj + 1], af[mi][0], af[mi][1], af[mi][2], af[mi][3],
                             bf[nj][1], bf[nj][3]);
                }
        }
        __syncthreads();
    }

    // ---------------- fused epilogue ----------------
    const int mw = m0 + wM * 32;
    const int nw = n0 + wN * 32;
    const int rl = lane >> 2;            // row within 8
    const int cl = (lane & 3) * 2;       // col pair

    if (mode == 0) {
        #pragma unroll
        for (int mi = 0; mi < 2; ++mi)
            #pragma unroll
            for (int ni = 0; ni < 4; ++ni) {
                const int n = nw + ni * 8 + cl;
                const float bb0 = bias[n], bb1 = bias[n + 1];
                #pragma unroll
                for (int hh = 0; hh < 2; ++hh) {
                    const int m = mw + mi * 16 + rl + hh * 8;
                    float v0 = tanhf(acc[mi][ni][2 * hh]     + bb0);
                    float v1 = tanhf(acc[mi][ni][2 * hh + 1] + bb1);
                    *(__nv_bfloat162*)(g_h + (size_t)m * HH + n) =
                        __floats2bfloat162_rn(v0, v1);
                }
            }
    } else {
        const float dt = ts[step + 1] - ts[step];
        #pragma unroll
        for (int mi = 0; mi < 2; ++mi)
            #pragma unroll
            for (int ni = 0; ni < 4; ++ni) {
                const int n = nw + ni * 8 + cl;
                const float bb0 = bias[n], bb1 = bias[n + 1];
                #pragma unroll
                for (int hh = 0; hh < 2; ++hh) {
                    const int m = mw + mi * 16 + rl + hh * 8;
                    const size_t off = (size_t)m * DD + n;
                    float kq0 = acc[mi][ni][2 * hh]     + bb0;
                    float kq1 = acc[mi][ni][2 * hh + 1] + bb1;
                    float2 y2 = *(const float2*)(g_y + off);
                    float ks0 = 0.f, ks1 = 0.f;
                    if (stage >= 2) {
                        float2 t = *(const float2*)(g_ks + off);
                        ks0 = t.x; ks1 = t.y;
                    }
                    float x0, x1;
                    if (stage == 4) {
                        const float w = dt * (1.0f / 6.0f);
                        x0 = y2.x + w * (ks0 + kq0);
                        x1 = y2.y + w * (ks1 + kq1);
                        *(float2*)(g_y + off) = make_float2(x0, x1);
                        *(float2*)(out + (size_t)(step + 1) * (BB * DD) + off) =
                            make_float2(x0, x1);
                    } else {
                        const float cf = (stage == 3) ? dt : 0.5f * dt;
                        const float wk = (stage == 1) ? 1.0f : 2.0f;
                        *(float2*)(g_ks + off) = make_float2(ks0 + wk * kq0, ks1 + wk * kq1);
                        x0 = y2.x + cf * kq0;
                        x1 = y2.y + cf * kq1;
                    }
                    *(__nv_bfloat162*)(g_x + off) = __floats2bfloat162_rn(x0, x1);
                }
            }
    }
}

// ---------------- launch ----------------
extern "C" void kernel_launch(void* const* d_in, const int* in_sizes, int n_in,
                              void* d_out, int out_size)
{
    const float* first = (const float*)d_in[0];
    const float* ts    = (const float*)d_in[1];
    const float* W1    = (const float*)d_in[2];
    const float* b1    = (const float*)d_in[3];
    const float* W2    = (const float*)d_in[4];
    const float* b2    = (const float*)d_in[5];
    float* out = (float*)d_out;

    init_weights<<<(DD * HH + 255) / 256, 256>>>(W1, W2);
    init_state<<<(BB * DD + 255) / 256, 256>>>(first, out);

    const dim3 blk(NTHREADS);
    const dim3 grid1(HH / BN, BB / BM);   // 16 x 16 = 256 CTAs
    const dim3 grid2(DD / BN, BB / BM);   // 8 x 16  = 128 CTAs

    for (int step = 0; step < TT - 1; ++step) {
        for (int stage = 1; stage <= 4; ++stage) {
            ode_gemm<<<grid1, blk>>>(0, stage, step, b1, ts, out);
            ode_gemm<<<grid2, blk>>>(1, stage, step, b2, ts, out);
        }
    }
}

// round 3
// speedup vs baseline: 1.0268x; 1.0268x over previous
#include <cuda_runtime.h>
#include <cuda_bf16.h>
#include <cstdint>
#include <math.h>

// Problem dims
#define BB 1024
#define DD 512
#define HH 1024
#define TT 64

#define NT 256           // 8 warps per CTA
#define GROUPS 8         // B / 128
#define JPG 16           // CTAs per group (n-slices)

// SMEM layout (bytes, after 1024-align)
#define OFF_A   0          // 2 x (128 rows x 128B) double buffer = 32768
#define OFF_W1  32768      // 8 chunks x 64 rows x 128B = 65536
#define OFF_W2  98304      // 16 chunks x 32 rows x 128B = 65536
#define SMEM_BYTES (163840 + 1024)

#define SWZ(x) ((x) ^ (((x) >> 3) & 0x70))

// ---------------- persistent state ----------------
__device__ float g_y[BB*DD];
__device__ float g_ks[BB*DD];
__device__ __nv_bfloat16 g_x[BB*DD];
__device__ __nv_bfloat16 g_h[BB*HH];
__device__ __nv_bfloat16 g_W1T[HH*DD];   // [H][D] K-major
__device__ __nv_bfloat16 g_W2T[DD*HH];   // [D][H] K-major
__device__ unsigned g_barrier[GROUPS * 32];   // counter per group, 128B apart

// ---------------- helpers ----------------
__device__ __forceinline__ uint32_t smem_u32(const void* p) {
    uint32_t a;
    asm("{ .reg .u64 t; cvta.to.shared.u64 t, %1; cvt.u32.u64 %0, t; }" : "=r"(a) : "l"(p));
    return a;
}
__device__ __forceinline__ void cp16(uint32_t s, const void* g) {
    asm volatile("cp.async.cg.shared.global [%0], [%1], 16;" :: "r"(s), "l"(g));
}
#define CP_COMMIT()  asm volatile("cp.async.commit_group;" ::: "memory")
#define CP_WAIT(n)   asm volatile("cp.async.wait_group %0;" :: "n"(n) : "memory")

__device__ __forceinline__ void ldm_x4(uint32_t& r0, uint32_t& r1, uint32_t& r2, uint32_t& r3,
                                       uint32_t addr) {
    asm volatile("ldmatrix.sync.aligned.m8n8.x4.shared.b16 {%0,%1,%2,%3}, [%4];"
                 : "=r"(r0), "=r"(r1), "=r"(r2), "=r"(r3) : "r"(addr));
}
__device__ __forceinline__ void mma16816(float* c, uint32_t a0, uint32_t a1, uint32_t a2,
                                         uint32_t a3, uint32_t b0, uint32_t b1) {
    asm volatile("mma.sync.aligned.m16n8k16.row.col.f32.bf16.bf16.f32 "
                 "{%0,%1,%2,%3}, {%4,%5,%6,%7}, {%8,%9}, {%0,%1,%2,%3};"
                 : "+f"(c[0]), "+f"(c[1]), "+f"(c[2]), "+f"(c[3])
                 : "r"(a0), "r"(a1), "r"(a2), "r"(a3), "r"(b0), "r"(b1));
}

// 16-CTA group barrier via L2 atomics (release/acquire pattern)
__device__ __forceinline__ void group_bar(unsigned* cnt, unsigned target) {
    __threadfence();
    __syncthreads();
    if (threadIdx.x == 0) {
        atomicAdd(cnt, 1u);
        while (*(volatile unsigned*)cnt < target) { __nanosleep(32); }
        __threadfence();
    }
    __syncthreads();
}

// ---------------- init kernels ----------------
__global__ void init_weights(const float* __restrict__ W1, const float* __restrict__ W2) {
    int i = blockIdx.x * blockDim.x + threadIdx.x;
    if (i >= DD * HH) return;
    { int d = i / HH, h = i % HH; g_W1T[h * DD + d] = __float2bfloat16(W1[i]); }
    { int h = i / DD, d = i % DD; g_W2T[d * HH + h] = __float2bfloat16(W2[i]); }
}
__global__ void init_state(const float* __restrict__ fp, float* __restrict__ out) {
    int i = blockIdx.x * blockDim.x + threadIdx.x;
    if (i < GROUPS * 32) g_barrier[i] = 0u;
    if (i >= BB * DD) return;
    float v = fp[i];
    g_y[i] = v;
    g_x[i] = __float2bfloat16(v);
    out[i] = v;                       // pred_y[t=0]
}

// ---------------- persistent fused RK4 solver ----------------
__global__ void __launch_bounds__(NT, 1)
ode_persistent(const float* __restrict__ b1, const float* __restrict__ b2,
               const float* __restrict__ ts, float* __restrict__ out)
{
    extern __shared__ char smraw[];
    const uint32_t sraw = smem_u32(smraw);
    const uint32_t sb   = (sraw + 1023u) & ~1023u;
    const uint32_t aBase  = sb + OFF_A;
    const uint32_t w1Base = sb + OFF_W1;
    const uint32_t w2Base = sb + OFF_W2;

    const int tid  = threadIdx.x;
    const int wid  = tid >> 5, lane = tid & 31;
    const int wM   = wid & 3;        // 4 warps along M (32 rows each)
    const int wN   = wid >> 2;       // 2 warps along N

    const int grp  = blockIdx.y;     // 0..7   -> m-block
    const int j    = blockIdx.x;     // 0..15  -> n-slice
    const int m0   = grp * 128;
    const int n1_0 = j * 64;         // GEMM1 output columns (of H)
    const int n2_0 = j * 32;         // GEMM2 output columns (of D)

    unsigned* cnt = &g_barrier[grp * 32];

    // ---- resident weight slices -> SMEM ----
    // W1 slice: rows n1_0..+64 of g_W1T [H][512]; 8 chunks x (64 rows x 128B)
    for (int v = tid; v < 4096; v += NT) {
        int c = v >> 9, w = v & 511;
        int r = w >> 3, kb = (w & 7) << 4;
        cp16(w1Base + c * 8192 + SWZ(r * 128 + kb),
             g_W1T + (size_t)(n1_0 + r) * DD + c * 64 + (kb >> 1));
    }
    // W2 slice: rows n2_0..+32 of g_W2T [D][1024]; 16 chunks x (32 rows x 128B)
    for (int v = tid; v < 4096; v += NT) {
        int c = v >> 8, w = v & 255;
        int r = w >> 3, kb = (w & 7) << 4;
        cp16(w2Base + c * 4096 + SWZ(r * 128 + kb),
             g_W2T + (size_t)(n2_0 + r) * HH + c * 64 + (kb >> 1));
    }
    CP_COMMIT();
    CP_WAIT(0);
    __syncthreads();

    const int rl = lane >> 2;         // epilogue row-in-8
    const int cl = (lane & 3) * 2;    // epilogue col pair
    unsigned bar_target = 0;

    for (int s = 0; s < (TT - 1) * 4; ++s) {
        const int step  = s >> 2;
        const int stage = (s & 3) + 1;

        // ================= GEMM1: h = tanh(x @ W1 + b1) =================
        bar_target += JPG;
        group_bar(cnt, bar_target);

        float acc[2][4][4];
        #pragma unroll
        for (int a = 0; a < 2; ++a)
            #pragma unroll
            for (int b = 0; b < 4; ++b)
                #pragma unroll
                for (int q = 0; q < 4; ++q) acc[a][b][q] = 0.f;

        const __nv_bfloat16* Ag1 = g_x + (size_t)m0 * DD;

        // preload chunk 0 (128 rows x 64 k)
        #pragma unroll
        for (int p = 0; p < 4; ++p) {
            int idx = p * NT + tid;
            int r = idx >> 3, kb = (idx & 7) << 4;
            cp16(aBase + SWZ(r * 128 + kb), Ag1 + (size_t)r * DD + (kb >> 1));
        }
        CP_COMMIT();

        #pragma unroll 1
        for (int c = 0; c < 8; ++c) {
            if (c < 7) {
                const uint32_t dst = aBase + ((c + 1) & 1) * 16384;
                const __nv_bfloat16* src = Ag1 + (c + 1) * 64;
                #pragma unroll
                for (int p = 0; p < 4; ++p) {
                    int idx = p * NT + tid;
                    int r = idx >> 3, kb = (idx & 7) << 4;
                    cp16(dst + SWZ(r * 128 + kb), src + (size_t)r * DD + (kb >> 1));
                }
                CP_COMMIT();
                CP_WAIT(1);
            } else {
                CP_WAIT(0);
            }
            __syncthreads();

            const uint32_t sA = aBase + (c & 1) * 16384;
            const uint32_t sB = w1Base + c * 8192;
            #pragma unroll
            for (int ks = 0; ks < 4; ++ks) {
                const int kb = (ks * 16 + ((lane >> 4) << 3)) * 2;
                uint32_t af[2][4], bf[2][4];
                #pragma unroll
                for (int mi = 0; mi < 2; ++mi) {
                    int r = wM * 32 + mi * 16 + (lane & 15);
                    ldm_x4(af[mi][0], af[mi][1], af[mi][2], af[mi][3], sA + SWZ(r * 128 + kb));
                }
                #pragma unroll
                for (int nj = 0; nj < 2; ++nj) {
                    int r = wN * 32 + nj * 16 + (lane & 15);
                    ldm_x4(bf[nj][0], bf[nj][1], bf[nj][2], bf[nj][3], sB + SWZ(r * 128 + kb));
                }
                #pragma unroll
                for (int mi = 0; mi < 2; ++mi)
                    #pragma unroll
                    for (int nj = 0; nj < 2; ++nj) {
                        mma16816(acc[mi][2 * nj],     af[mi][0], af[mi][1], af[mi][2], af[mi][3],
                                 bf[nj][0], bf[nj][2]);
                        mma16816(acc[mi][2 * nj + 1], af[mi][0], af[mi][1], af[mi][2], af[mi][3],
                                 bf[nj][1], bf[nj][3]);
                    }
            }
            __syncthreads();
        }

        // epilogue: tanh -> g_h
        #pragma unroll
        for (int mi = 0; mi < 2; ++mi)
            #pragma unroll
            for (int ni = 0; ni < 4; ++ni) {
                const int n = n1_0 + wN * 32 + ni * 8 + cl;
                const float bb0 = b1[n], bb1 = b1[n + 1];
                #pragma unroll
                for (int hh = 0; hh < 2; ++hh) {
                    const int m = m0 + wM * 32 + mi * 16 + rl + hh * 8;
                    float v0 = tanhf(acc[mi][ni][2 * hh]     + bb0);
                    float v1 = tanhf(acc[mi][ni][2 * hh + 1] + bb1);
                    *(__nv_bfloat162*)(g_h + (size_t)m * HH + n) = __floats2bfloat162_rn(v0, v1);
                }
            }

        // ================= GEMM2: k = h @ W2 + b2 ; RK4 update =================
        bar_target += JPG;
        group_bar(cnt, bar_target);

        float ac2[2][2][4];
        #pragma unroll
        for (int a = 0; a < 2; ++a)
            #pragma unroll
            for (int b = 0; b < 2; ++b)
                #pragma unroll
                for (int q = 0; q < 4; ++q) ac2[a][b][q] = 0.f;

        const __nv_bfloat16* Ag2 = g_h + (size_t)m0 * HH;

        #pragma unroll
        for (int p = 0; p < 4; ++p) {
            int idx = p * NT + tid;
            int r = idx >> 3, kb = (idx & 7) << 4;
            cp16(aBase + SWZ(r * 128 + kb), Ag2 + (size_t)r * HH + (kb >> 1));
        }
        CP_COMMIT();

        #pragma unroll 1
        for (int c = 0; c < 16; ++c) {
            if (c < 15) {
                const uint32_t dst = aBase + ((c + 1) & 1) * 16384;
                const __nv_bfloat16* src = Ag2 + (c + 1) * 64;
                #pragma unroll
                for (int p = 0; p < 4; ++p) {
                    int idx = p * NT + tid;
                    int r = idx >> 3, kb = (idx & 7) << 4;
                    cp16(dst + SWZ(r * 128 + kb), src + (size_t)r * HH + (kb >> 1));
                }
                CP_COMMIT();
                CP_WAIT(1);
            } else {
                CP_WAIT(0);
            }
            __syncthreads();

            const uint32_t sA = aBase + (c & 1) * 16384;
            const uint32_t sB = w2Base + c * 4096;
            #pragma unroll
            for (int ks = 0; ks < 4; ++ks) {
                const int kb = (ks * 16 + ((lane >> 4) << 3)) * 2;
                uint32_t af[2][4], bf[4];
                #pragma unroll
                for (int mi = 0; mi < 2; ++mi) {
                    int r = wM * 32 + mi * 16 + (lane & 15);
                    ldm_x4(af[mi][0], af[mi][1], af[mi][2], af[mi][3], sA + SWZ(r * 128 + kb));
                }
                {
                    int r = wN * 16 + (lane & 15);
                    ldm_x4(bf[0], bf[1], bf[2], bf[3], sB + SWZ(r * 128 + kb));
                }
                #pragma unroll
                for (int mi = 0; mi < 2; ++mi) {
                    mma16816(ac2[mi][0], af[mi][0], af[mi][1], af[mi][2], af[mi][3], bf[0], bf[2]);
                    mma16816(ac2[mi][1], af[mi][0], af[mi][1], af[mi][2], af[mi][3], bf[1], bf[3]);
                }
            }
            __syncthreads();
        }

        // RK4 epilogue
        const float dt = ts[step + 1] - ts[step];
        #pragma unroll
        for (int mi = 0; mi < 2; ++mi)
            #pragma unroll
            for (int ni = 0; ni < 2; ++ni) {
                const int n = n2_0 + wN * 16 + ni * 8 + cl;
                const float bb0 = b2[n], bb1 = b2[n + 1];
                #pragma unroll
                for (int hh = 0; hh < 2; ++hh) {
                    const int m = m0 + wM * 32 + mi * 16 + rl + hh * 8;
                    const size_t off = (size_t)m * DD + n;
                    float kq0 = ac2[mi][ni][2 * hh]     + bb0;
                    float kq1 = ac2[mi][ni][2 * hh + 1] + bb1;
                    float2 y2 = *(const float2*)(g_y + off);
                    float ks0 = 0.f, ks1 = 0.f;
                    if (stage >= 2) {
                        float2 t = *(const float2*)(g_ks + off);
                        ks0 = t.x; ks1 = t.y;
                    }
                    float x0, x1;
                    if (stage == 4) {
                        const float w = dt * (1.0f / 6.0f);
                        x0 = y2.x + w * (ks0 + kq0);
                        x1 = y2.y + w * (ks1 + kq1);
                        *(float2*)(g_y + off) = make_float2(x0, x1);
                        *(float2*)(out + (size_t)(step + 1) * (BB * DD) + off) = make_float2(x0, x1);
                    } else {
                        const float cf = (stage == 3) ? dt : 0.5f * dt;
                        const float wk = (stage == 1) ? 1.0f : 2.0f;
                        *(float2*)(g_ks + off) = make_float2(ks0 + wk * kq0, ks1 + wk * kq1);
                        x0 = y2.x + cf * kq0;
                        x1 = y2.y + cf * kq1;
                    }
                    *(__nv_bfloat162*)(g_x + off) = __floats2bfloat162_rn(x0, x1);
                }
            }
    }
}

// ---------------- launch ----------------
extern "C" void kernel_launch(void* const* d_in, const int* in_sizes, int n_in,
                              void* d_out, int out_size)
{
    const float* first = (const float*)d_in[0];
    const float* ts    = (const float*)d_in[1];
    const float* W1    = (const float*)d_in[2];
    const float* b1    = (const float*)d_in[3];
    const float* W2    = (const float*)d_in[4];
    const float* b2    = (const float*)d_in[5];
    float* out = (float*)d_out;

    static bool configured = false;
    if (!configured) {
        cudaFuncSetAttribute(ode_persistent, cudaFuncAttributeMaxDynamicSharedMemorySize,
                             SMEM_BYTES);
        configured = true;
    }

    init_weights<<<(DD * HH + 255) / 256, 256>>>(W1, W2);
    init_state<<<(BB * DD + 255) / 256, 256>>>(first, out);
    ode_persistent<<<dim3(JPG, GROUPS), NT, SMEM_BYTES>>>(b1, b2, ts, out);
}